// round 1
// baseline (speedup 1.0000x reference)
#include <cuda_runtime.h>
#include <stdint.h>

// Shapes (fixed for this problem)
#define T_    4
#define B_    64
#define C_    384
#define N_    196
#define NH_   8
#define D_    48
#define BNN   (B_*N_)      // 12544
#define TBN   (T_*BNN)     // 50176
#define CN    (C_*N_)      // 75264
#define BCN   (B_*CN)      // 4816896
#define TBCN  (T_*BCN)     // 19267584

// ---------------- device scratch (static; no runtime allocation) ----------------
__device__ uint8_t g_xs[(size_t)C_*TBN];        // input spikes,  layout [c][t][b][n]
__device__ float   g_y [(size_t)3*C_*TBN];      // BN'd q/k/v pre-LIF, [br][c][t][b][n]
__device__ uint8_t g_s [(size_t)3*C_*TBN];      // q/k/v spikes
__device__ float   g_ya[(size_t)C_*TBN];        // attention output pre-LIF
__device__ uint8_t g_sa[(size_t)C_*TBN];        // attn spikes

// ---------------- LIF kernels (replicate reference fp32 op order exactly) -------
__global__ void k_lif_in(const float* __restrict__ x)
{
    int i = blockIdx.x*blockDim.x + threadIdx.x;
    if (i >= BCN) return;
    int b = i / CN; int r = i - b*CN; int c = r / N_; int n = r - c*N_;
    size_t dst = (size_t)c*TBN + (size_t)b*N_ + n;
    float v = 0.0f;
    #pragma unroll
    for (int t = 0; t < T_; t++) {
        float xv = x[(size_t)t*BCN + i];
        v = __fadd_rn(v, __fmul_rn(__fsub_rn(xv, v), 0.5f));   // v += (x - v)/2
        uint8_t s = (v >= 1.0f);
        if (s) v = 0.0f;
        g_xs[dst + (size_t)t*BNN] = s;
    }
}

__global__ void k_lif_qkv()
{
    size_t i = (size_t)blockIdx.x*blockDim.x + threadIdx.x;
    if (i >= (size_t)3*C_*BNN) return;
    size_t row = i / BNN; size_t j = i - row*BNN;
    const float* yp = g_y + row*TBN + j;
    uint8_t*     sp = g_s + row*TBN + j;
    float v = 0.0f;
    #pragma unroll
    for (int t = 0; t < T_; t++) {
        v = __fadd_rn(v, __fmul_rn(__fsub_rn(yp[(size_t)t*BNN], v), 0.5f));
        uint8_t s = (v >= 1.0f);
        if (s) v = 0.0f;
        sp[(size_t)t*BNN] = s;
    }
}

__global__ void k_lif_attn()
{
    size_t i = (size_t)blockIdx.x*blockDim.x + threadIdx.x;
    if (i >= (size_t)C_*BNN) return;
    size_t row = i / BNN; size_t j = i - row*BNN;
    const float* yp = g_ya + row*TBN + j;
    uint8_t*     sp = g_sa + row*TBN + j;
    float v = 0.0f;
    #pragma unroll
    for (int t = 0; t < T_; t++) {
        v = __fadd_rn(v, __fmul_rn(__fsub_rn(yp[(size_t)t*BNN], v), 0.5f));
        uint8_t s = (v >= 0.5f);
        if (s) v = 0.0f;
        sp[(size_t)t*BNN] = s;
    }
}

// ---------------- fp32 GEMM core: Y[128x128 tile] = W[M,K] * X[K, TBN] ----------
// A fp32 row-major (lda=384), B uint8 spikes (ldb=TBN). 256 threads, 8x8 per thread.
__device__ __forceinline__ void gemm_acc(
    const float* __restrict__ A, const uint8_t* __restrict__ Bx,
    int m0, int n0, float (&acc)[8][8],
    float (*As)[36], float (*Bs)[128])
{
    int tid = threadIdx.x;
    int tx = tid & 15, ty = tid >> 4;
    for (int k0 = 0; k0 < C_; k0 += 32) {
        #pragma unroll
        for (int i = 0; i < 4; i++) {
            int idx = tid + i*256; int row = idx >> 3; int c4 = idx & 7;
            float4 v = *(const float4*)(A + (size_t)(m0+row)*C_ + k0 + c4*4);
            *(float4*)&As[row][c4*4] = v;
        }
        #pragma unroll
        for (int i = 0; i < 4; i++) {
            int idx = tid + i*256; int row = idx >> 5; int c4 = idx & 31;
            uchar4 u = *(const uchar4*)(Bx + (size_t)(k0+row)*TBN + n0 + c4*4);
            Bs[row][c4*4+0] = (float)u.x; Bs[row][c4*4+1] = (float)u.y;
            Bs[row][c4*4+2] = (float)u.z; Bs[row][c4*4+3] = (float)u.w;
        }
        __syncthreads();
        #pragma unroll
        for (int k = 0; k < 32; k++) {
            float a[8], b[8];
            #pragma unroll
            for (int i = 0; i < 8; i++) a[i] = As[ty*8+i][k];
            float4 b0 = *(const float4*)&Bs[k][tx*8];
            float4 b1 = *(const float4*)&Bs[k][tx*8+4];
            b[0]=b0.x; b[1]=b0.y; b[2]=b0.z; b[3]=b0.w;
            b[4]=b1.x; b[5]=b1.y; b[6]=b1.z; b[7]=b1.w;
            #pragma unroll
            for (int i = 0; i < 8; i++)
                #pragma unroll
                for (int j = 0; j < 8; j++)
                    acc[i][j] += a[i]*b[j];
        }
        __syncthreads();
    }
}

// q/k/v projection + BN epilogue. grid = (392, 3, 3[branch])
__global__ __launch_bounds__(256) void k_gemm_qkv(
    const float* __restrict__ Wq, const float* __restrict__ Wk, const float* __restrict__ Wv,
    const float* __restrict__ Pq, const float* __restrict__ Pk, const float* __restrict__ Pv)
{
    __shared__ float As[128][36];
    __shared__ float Bs[32][128];
    int br = blockIdx.z;
    const float* A = (br==0) ? Wq : ((br==1) ? Wk : Wv);
    const float* P = (br==0) ? Pq : ((br==1) ? Pk : Pv);
    float* Yo = g_y + (size_t)br*C_*TBN;
    int m0 = blockIdx.y*128, n0 = blockIdx.x*128;
    float acc[8][8];
    #pragma unroll
    for (int i = 0; i < 8; i++)
        #pragma unroll
        for (int j = 0; j < 8; j++) acc[i][j] = 0.0f;
    gemm_acc(A, g_xs, m0, n0, acc, As, Bs);
    int tx = threadIdx.x & 15, ty = threadIdx.x >> 4;
    #pragma unroll
    for (int i = 0; i < 8; i++) {
        int d = m0 + ty*8 + i;
        float g  = P[d], be = P[C_+d], mn = P[2*C_+d], va = P[3*C_+d];
        float inv = g / sqrtf(va + 1e-5f);
        float ad  = be - mn*inv;
        float* yr = Yo + (size_t)d*TBN + n0 + tx*8;
        #pragma unroll
        for (int j = 0; j < 8; j++) yr[j] = acc[i][j]*inv + ad;
    }
}

// proj GEMM + bias + BN + identity add; writes final output. grid = (392, 3)
__global__ __launch_bounds__(256) void k_gemm_proj(
    const float* __restrict__ W, const float* __restrict__ bias,
    const float* __restrict__ P, const float* __restrict__ x,
    float* __restrict__ out)
{
    __shared__ float As[128][36];
    __shared__ float Bs[32][128];
    int m0 = blockIdx.y*128, n0 = blockIdx.x*128;
    float acc[8][8];
    #pragma unroll
    for (int i = 0; i < 8; i++)
        #pragma unroll
        for (int j = 0; j < 8; j++) acc[i][j] = 0.0f;
    gemm_acc(W, g_sa, m0, n0, acc, As, Bs);
    int tx = threadIdx.x & 15, ty = threadIdx.x >> 4;
    #pragma unroll
    for (int i = 0; i < 8; i++) {
        int d = m0 + ty*8 + i;
        float g  = P[d], be = P[C_+d], mn = P[2*C_+d], va = P[3*C_+d];
        float inv = g / sqrtf(va + 1e-5f);
        float ad  = be - mn*inv;
        float bb  = bias[d];
        #pragma unroll
        for (int j = 0; j < 8; j++) {
            int col = n0 + tx*8 + j;
            int t = col / BNN; int r = col - t*BNN; int b = r / N_; int n = r - b*N_;
            size_t oi = (size_t)t*BCN + (size_t)b*CN + (size_t)d*N_ + n;
            out[oi] = (acc[i][j] + bb)*inv + ad + x[oi];
        }
    }
}

// ---------------- attention: y = q @ (k^T v), all-integer (exact) ---------------
// grid = T*B*NH = 2048 blocks, 256 threads. Bitpacked 48-bit spike rows.
__global__ __launch_bounds__(256) void k_attn()
{
    __shared__ uint8_t tile[48][200];
    __shared__ unsigned long long qp[196];
    __shared__ unsigned long long km[48][4];
    __shared__ unsigned long long vm[48][4];
    __shared__ int kv[48][49];              // stride 49 -> conflict-free phase-3 reads

    int tid = threadIdx.x;
    int blk = blockIdx.x;
    int h = blk & 7; int tb = blk >> 3; int b = tb & 63; int t = tb >> 6;
    size_t jbase = (size_t)t*BNN + (size_t)b*N_;
    const uint8_t* qbp = g_s + (size_t)(h*D_)*TBN + jbase;
    const uint8_t* kbp = qbp + (size_t)C_*TBN;
    const uint8_t* vbp = kbp + (size_t)C_*TBN;

    // zero tile pad cols [196,200) once (k/v packing reads past 196)
    if (tid < 48) { tile[tid][196]=0; tile[tid][197]=0; tile[tid][198]=0; tile[tid][199]=0; }

    // ---- K tile -> km ----
    for (int i = tid; i < 48*49; i += 256) {
        int c = i/49, g4 = i - c*49;
        *(uchar4*)&tile[c][g4*4] = *(const uchar4*)(kbp + (size_t)c*TBN + g4*4);
    }
    __syncthreads();
    if (tid < 192) {
        int c = tid >> 2, w = tid & 3;
        const unsigned long long* rw = (const unsigned long long*)&tile[c][0];
        unsigned long long bits;
        if (w < 3) {
            bits = 0ULL;
            #pragma unroll
            for (int jj = 0; jj < 8; jj++)
                bits |= ((rw[w*8+jj] * 0x0102040810204080ULL) >> 56) << (8*jj);
        } else {
            bits = ((rw[24] * 0x0102040810204080ULL) >> 56) & 0xFULL;  // m = 192..195
        }
        km[c][w] = bits;
    }
    __syncthreads();

    // ---- V tile -> vm ----
    for (int i = tid; i < 48*49; i += 256) {
        int c = i/49, g4 = i - c*49;
        *(uchar4*)&tile[c][g4*4] = *(const uchar4*)(vbp + (size_t)c*TBN + g4*4);
    }
    __syncthreads();
    if (tid < 192) {
        int c = tid >> 2, w = tid & 3;
        const unsigned long long* rw = (const unsigned long long*)&tile[c][0];
        unsigned long long bits;
        if (w < 3) {
            bits = 0ULL;
            #pragma unroll
            for (int jj = 0; jj < 8; jj++)
                bits |= ((rw[w*8+jj] * 0x0102040810204080ULL) >> 56) << (8*jj);
        } else {
            bits = ((rw[24] * 0x0102040810204080ULL) >> 56) & 0xFULL;
        }
        vm[c][w] = bits;
    }
    __syncthreads();

    // ---- Q tile ----
    for (int i = tid; i < 48*49; i += 256) {
        int c = i/49, g4 = i - c*49;
        *(uchar4*)&tile[c][g4*4] = *(const uchar4*)(qbp + (size_t)c*TBN + g4*4);
    }
    __syncthreads();

    // qp (tid<196) and kv = k^T v via popcount (all threads)
    if (tid < 196) {
        unsigned long long q = 0ULL;
        #pragma unroll
        for (int dd = 0; dd < 48; dd++)
            q |= ((unsigned long long)tile[dd][tid]) << dd;
        qp[tid] = q;
    }
    for (int i = tid; i < 48*48; i += 256) {
        int cc = i/48, d2 = i - cc*48;
        int s = 0;
        #pragma unroll
        for (int w = 0; w < 4; w++) s += __popcll(km[cc][w] & vm[d2][w]);
        kv[cc][d2] = s;
    }
    __syncthreads();

    // y[n, dd] = sum over set bits c of qp[n] of kv[c][dd]; scaled by 0.125
    if (tid < 196) {
        int y[48];
        #pragma unroll
        for (int dd = 0; dd < 48; dd++) y[dd] = 0;
        unsigned long long m = qp[tid];
        while (m) {
            int c = __ffsll((long long)m) - 1;
            m &= m - 1;
            const int* row = kv[c];
            #pragma unroll
            for (int dd = 0; dd < 48; dd++) y[dd] += row[dd];
        }
        float* ob = g_ya + (size_t)(h*D_)*TBN + jbase + tid;
        #pragma unroll
        for (int dd = 0; dd < 48; dd++)
            ob[(size_t)dd*TBN] = (float)y[dd] * 0.125f;
    }
}

// ---------------- launch --------------------------------------------------------
extern "C" void kernel_launch(void* const* d_in, const int* in_sizes, int n_in,
                              void* d_out, int out_size)
{
    const float* x   = (const float*)d_in[0];
    const float* qw  = (const float*)d_in[1];
    const float* kw  = (const float*)d_in[2];
    const float* vw  = (const float*)d_in[3];
    const float* pw  = (const float*)d_in[4];
    const float* pb  = (const float*)d_in[5];
    const float* qbn = (const float*)d_in[6];
    const float* kbn = (const float*)d_in[7];
    const float* vbn = (const float*)d_in[8];
    const float* pbn = (const float*)d_in[9];
    float* out = (float*)d_out;

    k_lif_in<<<(BCN + 255)/256, 256>>>(x);
    k_gemm_qkv<<<dim3(TBN/128, C_/128, 3), 256>>>(qw, kw, vw, qbn, kbn, vbn);
    k_lif_qkv<<<(3*C_*BNN + 255)/256, 256>>>();
    k_attn<<<T_*B_*NH_, 256>>>();
    k_lif_attn<<<(C_*BNN + 255)/256, 256>>>();
    k_gemm_proj<<<dim3(TBN/128, C_/128), 256>>>(pw, pb, pbn, x, out);
}